// round 2
// baseline (speedup 1.0000x reference)
#include <cuda_runtime.h>
#include <cuda_bf16.h>

// SmoothLDDTLoss — b=2, n=4096.
// Upper-triangle (sum symmetric, diagonal excluded) -> 16.78M pairs total.
// Per pair: 2 MUFU (sqrt.approx) + shared-mem LUT for the 4-sigmoid sum.
// IR=2 register row-blocking: 256-row i-tile x 128-col j-tile per CTA.

#define NTOK 4096
#define TJ 128
#define TI 256
#define NTI (NTOK / TI)   // 16
#define NTJ (NTOK / TJ)   // 32

#define TBL_N 1024
#define TBL_H 0.015625f          // 16 / 1024
#define TBL_SCALE 64.0f          // 1 / H
#define DD_CLAMP 15.984375f      // 1023 * H

// accumulators: [num0, den0, num1, den1]
__device__ double g_acc[4];

__global__ void init_kernel() {
    g_acc[0] = 0.0; g_acc[1] = 0.0; g_acc[2] = 0.0; g_acc[3] = 0.0;
}

__device__ __forceinline__ float fsqrt_approx(float x) {
    float r;
    asm("sqrt.approx.f32 %0, %1;" : "=f"(r) : "f"(x));
    return r;
}

// exact-ish sum of 4 sigmoids: sigma(0.5-x)+sigma(1-x)+sigma(2-x)+sigma(4-x)
__device__ __forceinline__ float sig4(float x) {
    float s = 0.0f;
    s += __fdividef(1.0f, 1.0f + __expf(x - 0.5f));
    s += __fdividef(1.0f, 1.0f + __expf(x - 1.0f));
    s += __fdividef(1.0f, 1.0f + __expf(x - 2.0f));
    s += __fdividef(1.0f, 1.0f + __expf(x - 4.0f));
    return s;
}

__device__ __forceinline__ float lut_eval(float dd, const float2* __restrict__ tbl) {
    float t = dd * TBL_SCALE;
    int k = (int)t;
    float frac = t - (float)k;
    float2 e = tbl[k];
    return fmaf(frac, e.y, e.x);
}

__device__ __forceinline__ void accum_pair(
    float px, float py, float pz, float tx, float ty, float tz,
    float nuc675, float cm,
    float4 jp, float4 jt, const float2* __restrict__ tbl,
    float& num, float& den, bool active)
{
    float dx = px - jp.x, dy = py - jp.y, dz = pz - jp.z;
    float d2p = fmaf(dx, dx, fmaf(dy, dy, dz * dz));
    float ex = tx - jt.x, ey = ty - jt.y, ez = tz - jt.z;
    float d2t = fmaf(ex, ex, fmaf(ey, ey, ez * ez));

    float cut2 = fmaf(jp.w, nuc675, 225.0f);            // 225 or 900
    float m = (d2t < cut2 && active) ? cm * jt.w : 0.0f;

    float dd = fminf(fabsf(fsqrt_approx(d2t) - fsqrt_approx(d2p)), DD_CLAMP);
    float v = lut_eval(dd, tbl);                        // = 4 * eps

    num = fmaf(v, m, num);
    den += m;
}

__global__ void __launch_bounds__(128)
lddt_kernel(const float* __restrict__ pred,
            const float* __restrict__ truec,
            const int* __restrict__ is_dna,
            const int* __restrict__ is_rna,
            const int* __restrict__ cmask)
{
    const int I = blockIdx.x;
    const int J = blockIdx.y;
    if (J < 2 * I) return;                 // tile entirely below diagonal
    const int b = blockIdx.z;
    const int tid = threadIdx.x;

    __shared__ float2 tbl[TBL_N];          // (value, delta) pairs
    __shared__ float4 sjp[TJ];             // pred xyz, w = nuc flag
    __shared__ float4 sjt[TJ];             // true xyz, w = coords_mask

    // fill sigmoid-sum table
    for (int k = tid; k < TBL_N; k += 128) {
        float x0 = (float)k * TBL_H;
        float v0 = sig4(x0);
        float v1 = sig4(x0 + TBL_H);
        tbl[k] = make_float2(v0, v1 - v0);
    }

    const int base = b * NTOK;

    // stage j-tile
    {
        const int jg = base + J * TJ + tid;
        float4 p, t;
        p.x = pred[3 * jg + 0]; p.y = pred[3 * jg + 1]; p.z = pred[3 * jg + 2];
        t.x = truec[3 * jg + 0]; t.y = truec[3 * jg + 1]; t.z = truec[3 * jg + 2];
        p.w = (is_dna[jg] != 0 || is_rna[jg] != 0) ? 1.0f : 0.0f;
        t.w = (cmask[jg] != 0) ? 1.0f : 0.0f;
        sjp[tid] = p;
        sjt[tid] = t;
    }

    // own rows: r0 = 256*I + tid, r1 = r0 + 128
    const int ig0 = base + I * TI + tid;
    const int ig1 = ig0 + 128;
    const float p0x = pred[3 * ig0 + 0], p0y = pred[3 * ig0 + 1], p0z = pred[3 * ig0 + 2];
    const float t0x = truec[3 * ig0 + 0], t0y = truec[3 * ig0 + 1], t0z = truec[3 * ig0 + 2];
    const float p1x = pred[3 * ig1 + 0], p1y = pred[3 * ig1 + 1], p1z = pred[3 * ig1 + 2];
    const float t1x = truec[3 * ig1 + 0], t1y = truec[3 * ig1 + 1], t1z = truec[3 * ig1 + 2];
    const float nuc0 = (is_dna[ig0] != 0 || is_rna[ig0] != 0) ? 675.0f : 0.0f;
    const float nuc1 = (is_dna[ig1] != 0 || is_rna[ig1] != 0) ? 675.0f : 0.0f;
    const float cm0 = (cmask[ig0] != 0) ? 1.0f : 0.0f;
    const float cm1 = (cmask[ig1] != 0) ? 1.0f : 0.0f;

    __syncthreads();

    float n0 = 0.0f, d0 = 0.0f, n1 = 0.0f, d1 = 0.0f;

    if (J >= 2 * I + 2) {
        // hot path: fully above diagonal, branch-free
        #pragma unroll 4
        for (int j = 0; j < TJ; ++j) {
            float4 jp = sjp[j];
            float4 jt = sjt[j];
            accum_pair(p0x, p0y, p0z, t0x, t0y, t0z, nuc0, cm0, jp, jt, tbl, n0, d0, true);
            accum_pair(p1x, p1y, p1z, t1x, t1y, t1z, nuc1, cm1, jp, jt, tbl, n1, d1, true);
        }
    } else if (J == 2 * I) {
        // row0 triangular (j > tid), row1 entirely below diagonal
        for (int j = tid + 1; j < TJ; ++j) {
            float4 jp = sjp[j];
            float4 jt = sjt[j];
            accum_pair(p0x, p0y, p0z, t0x, t0y, t0z, nuc0, cm0, jp, jt, tbl, n0, d0, true);
        }
    } else {
        // J == 2*I + 1: row0 full, row1 triangular (j > tid)
        #pragma unroll 2
        for (int j = 0; j < TJ; ++j) {
            float4 jp = sjp[j];
            float4 jt = sjt[j];
            accum_pair(p0x, p0y, p0z, t0x, t0y, t0z, nuc0, cm0, jp, jt, tbl, n0, d0, true);
            accum_pair(p1x, p1y, p1z, t1x, t1y, t1z, nuc1, cm1, jp, jt, tbl, n1, d1, j > tid);
        }
    }

    float acc_num = n0 + n1;
    float acc_den = d0 + d1;

    // block reduce (4 warps)
    #pragma unroll
    for (int o = 16; o > 0; o >>= 1) {
        acc_num += __shfl_xor_sync(0xFFFFFFFFu, acc_num, o);
        acc_den += __shfl_xor_sync(0xFFFFFFFFu, acc_den, o);
    }
    __shared__ float rn[4], rd[4];
    const int wid = tid >> 5;
    if ((tid & 31) == 0) { rn[wid] = acc_num; rd[wid] = acc_den; }
    __syncthreads();
    if (tid == 0) {
        float tn = rn[0] + rn[1] + rn[2] + rn[3];
        float td = rd[0] + rd[1] + rd[2] + rd[3];
        atomicAdd(&g_acc[2 * b + 0], (double)tn);
        atomicAdd(&g_acc[2 * b + 1], (double)td);
    }
}

__global__ void final_kernel(float* __restrict__ out) {
    // full-matrix sums = 2 * upper-triangle sums; eps = 0.25 * sum4
    double l0, l1;
    {
        double num = 2.0 * 0.25 * g_acc[0];
        double den = 2.0 * g_acc[1];
        if (den < 1.0) den = 1.0;
        l0 = num / den;
    }
    {
        double num = 2.0 * 0.25 * g_acc[2];
        double den = 2.0 * g_acc[3];
        if (den < 1.0) den = 1.0;
        l1 = num / den;
    }
    out[0] = (float)(1.0 - 0.5 * (l0 + l1));
}

extern "C" void kernel_launch(void* const* d_in, const int* in_sizes, int n_in,
                              void* d_out, int out_size) {
    const float* pred  = (const float*)d_in[0];
    const float* truec = (const float*)d_in[1];
    const int*   dna   = (const int*)d_in[2];
    const int*   rna   = (const int*)d_in[3];
    const int*   cm    = (const int*)d_in[4];

    init_kernel<<<1, 1>>>();
    dim3 grid(NTI, NTJ, 2);
    lddt_kernel<<<grid, 128>>>(pred, truec, dna, rna, cm);
    final_kernel<<<1, 1>>>((float*)d_out);
}

// round 3
// speedup vs baseline: 1.3756x; 1.3756x over previous
#include <cuda_runtime.h>
#include <cuda_bf16.h>

// SmoothLDDTLoss — b=2, n=4096. Single-kernel fused version.
// Upper-triangle (sum symmetric, diagonal excluded) -> 16.78M pairs total.
// Per pair: 2 MUFU (sqrt.approx) + shared-mem LUT for the 4-sigmoid sum.
// IR=2 register row-blocking: 256-row i-tile x 128-col j-tile per CTA.
// Compacted tile list: 272 valid tiles/batch, 544 CTAs total (one wave).
// Last-CTA-done finalize; accumulators self-reset for graph replay.

#define NTOK 4096
#define TJ 128
#define TI 256
#define NTILES_B 272              // sum_{I=0}^{15} (32 - 2I)
#define TOTAL_CTAS (2 * NTILES_B)

#define TBL_N 1024
#define TBL_H 0.015625f           // 16 / 1024
#define TBL_SCALE 64.0f
#define DD_CLAMP 15.984375f       // 1023 * H

// accumulators: [num0, den0, num1, den1]; zero-init at load, reset by last CTA
__device__ double g_acc[4];
__device__ int g_done;

__device__ __forceinline__ float fsqrt_approx(float x) {
    float r;
    asm("sqrt.approx.f32 %0, %1;" : "=f"(r) : "f"(x));
    return r;
}

__device__ __forceinline__ float sig4(float x) {
    float s = 0.0f;
    s += __fdividef(1.0f, 1.0f + __expf(x - 0.5f));
    s += __fdividef(1.0f, 1.0f + __expf(x - 1.0f));
    s += __fdividef(1.0f, 1.0f + __expf(x - 2.0f));
    s += __fdividef(1.0f, 1.0f + __expf(x - 4.0f));
    return s;
}

__device__ __forceinline__ void accum_pair(
    float px, float py, float pz, float tx, float ty, float tz,
    float nuc675, float cm,
    float4 jp, float4 jt, const float2* __restrict__ tbl,
    float& num, float& den, bool active)
{
    float dx = px - jp.x, dy = py - jp.y, dz = pz - jp.z;
    float d2p = fmaf(dx, dx, fmaf(dy, dy, dz * dz));
    float ex = tx - jt.x, ey = ty - jt.y, ez = tz - jt.z;
    float d2t = fmaf(ex, ex, fmaf(ey, ey, ez * ez));

    float cut2 = fmaf(jp.w, nuc675, 225.0f);            // 225 or 900
    float m = (d2t < cut2 && active) ? cm * jt.w : 0.0f;

    float dd = fminf(fabsf(fsqrt_approx(d2t) - fsqrt_approx(d2p)), DD_CLAMP);
    float t = dd * TBL_SCALE;
    int k = (int)t;
    float frac = t - (float)k;
    float2 e = tbl[k];
    float v = fmaf(frac, e.y, e.x);                     // = 4 * eps

    num = fmaf(v, m, num);
    den += m;
}

__global__ void __launch_bounds__(128)
lddt_fused(const float* __restrict__ pred,
           const float* __restrict__ truec,
           const int* __restrict__ is_dna,
           const int* __restrict__ is_rna,
           const int* __restrict__ cmask,
           float* __restrict__ out)
{
    // decode (batch, I, J) from compacted linear tile id
    int lin = blockIdx.x;
    const int b = (lin >= NTILES_B) ? 1 : 0;
    lin -= b * NTILES_B;
    int I = 0;
    {
        int cnt = 32;                  // 32 - 2I tiles in row I
        while (lin >= cnt) { lin -= cnt; I++; cnt -= 2; }
    }
    const int J = 2 * I + lin;

    const int tid = threadIdx.x;

    __shared__ float2 tbl[TBL_N];
    __shared__ float4 sjp[TJ];         // pred xyz, w = nuc flag
    __shared__ float4 sjt[TJ];         // true xyz, w = coords_mask

    for (int k = tid; k < TBL_N; k += 128) {
        float x0 = (float)k * TBL_H;
        float v0 = sig4(x0);
        float v1 = sig4(x0 + TBL_H);
        tbl[k] = make_float2(v0, v1 - v0);
    }

    const int base = b * NTOK;

    {
        const int jg = base + J * TJ + tid;
        float4 p, t;
        p.x = pred[3 * jg + 0]; p.y = pred[3 * jg + 1]; p.z = pred[3 * jg + 2];
        t.x = truec[3 * jg + 0]; t.y = truec[3 * jg + 1]; t.z = truec[3 * jg + 2];
        p.w = (is_dna[jg] != 0 || is_rna[jg] != 0) ? 1.0f : 0.0f;
        t.w = (cmask[jg] != 0) ? 1.0f : 0.0f;
        sjp[tid] = p;
        sjt[tid] = t;
    }

    const int ig0 = base + I * TI + tid;
    const int ig1 = ig0 + 128;
    const float p0x = pred[3 * ig0 + 0], p0y = pred[3 * ig0 + 1], p0z = pred[3 * ig0 + 2];
    const float t0x = truec[3 * ig0 + 0], t0y = truec[3 * ig0 + 1], t0z = truec[3 * ig0 + 2];
    const float p1x = pred[3 * ig1 + 0], p1y = pred[3 * ig1 + 1], p1z = pred[3 * ig1 + 2];
    const float t1x = truec[3 * ig1 + 0], t1y = truec[3 * ig1 + 1], t1z = truec[3 * ig1 + 2];
    const float nuc0 = (is_dna[ig0] != 0 || is_rna[ig0] != 0) ? 675.0f : 0.0f;
    const float nuc1 = (is_dna[ig1] != 0 || is_rna[ig1] != 0) ? 675.0f : 0.0f;
    const float cm0 = (cmask[ig0] != 0) ? 1.0f : 0.0f;
    const float cm1 = (cmask[ig1] != 0) ? 1.0f : 0.0f;

    __syncthreads();

    float n0 = 0.0f, d0 = 0.0f, n1 = 0.0f, d1 = 0.0f;

    if (J >= 2 * I + 2) {
        #pragma unroll 4
        for (int j = 0; j < TJ; ++j) {
            float4 jp = sjp[j];
            float4 jt = sjt[j];
            accum_pair(p0x, p0y, p0z, t0x, t0y, t0z, nuc0, cm0, jp, jt, tbl, n0, d0, true);
            accum_pair(p1x, p1y, p1z, t1x, t1y, t1z, nuc1, cm1, jp, jt, tbl, n1, d1, true);
        }
    } else if (J == 2 * I) {
        for (int j = tid + 1; j < TJ; ++j) {
            float4 jp = sjp[j];
            float4 jt = sjt[j];
            accum_pair(p0x, p0y, p0z, t0x, t0y, t0z, nuc0, cm0, jp, jt, tbl, n0, d0, true);
        }
    } else {  // J == 2*I + 1
        #pragma unroll 2
        for (int j = 0; j < TJ; ++j) {
            float4 jp = sjp[j];
            float4 jt = sjt[j];
            accum_pair(p0x, p0y, p0z, t0x, t0y, t0z, nuc0, cm0, jp, jt, tbl, n0, d0, true);
            accum_pair(p1x, p1y, p1z, t1x, t1y, t1z, nuc1, cm1, jp, jt, tbl, n1, d1, j > tid);
        }
    }

    float acc_num = n0 + n1;
    float acc_den = d0 + d1;

    #pragma unroll
    for (int o = 16; o > 0; o >>= 1) {
        acc_num += __shfl_xor_sync(0xFFFFFFFFu, acc_num, o);
        acc_den += __shfl_xor_sync(0xFFFFFFFFu, acc_den, o);
    }
    __shared__ float rn[4], rd[4];
    const int wid = tid >> 5;
    if ((tid & 31) == 0) { rn[wid] = acc_num; rd[wid] = acc_den; }
    __syncthreads();

    if (tid == 0) {
        float tn = rn[0] + rn[1] + rn[2] + rn[3];
        float td = rd[0] + rd[1] + rd[2] + rd[3];
        atomicAdd(&g_acc[2 * b + 0], (double)tn);
        atomicAdd(&g_acc[2 * b + 1], (double)td);
        __threadfence();
        int done = atomicAdd(&g_done, 1);
        if (done == TOTAL_CTAS - 1) {
            // last CTA: finalize, then reset state for the next replay
            volatile double* acc = g_acc;
            double num0 = acc[0], den0 = acc[1], num1 = acc[2], den1 = acc[3];
            double e0 = 2.0 * den0; if (e0 < 1.0) e0 = 1.0;
            double e1 = 2.0 * den1; if (e1 < 1.0) e1 = 1.0;
            double l0 = (0.5 * num0) / e0;   // 2 * 0.25 * num / (2*den)
            double l1 = (0.5 * num1) / e1;
            out[0] = (float)(1.0 - 0.5 * (l0 + l1));
            acc[0] = 0.0; acc[1] = 0.0; acc[2] = 0.0; acc[3] = 0.0;
            g_done = 0;
            __threadfence();
        }
    }
}

extern "C" void kernel_launch(void* const* d_in, const int* in_sizes, int n_in,
                              void* d_out, int out_size) {
    const float* pred  = (const float*)d_in[0];
    const float* truec = (const float*)d_in[1];
    const int*   dna   = (const int*)d_in[2];
    const int*   rna   = (const int*)d_in[3];
    const int*   cm    = (const int*)d_in[4];

    lddt_fused<<<TOTAL_CTAS, 128>>>(pred, truec, dna, rna, cm, (float*)d_out);
}